// round 15
// baseline (speedup 1.0000x reference)
#include <cuda_runtime.h>
#include <cuda_bf16.h>
#include <math.h>
#include <stdint.h>

// ---------------------------------------------------------------------------
// SwinTransformer block, B=128, FMAP=56, WS=7, SHIFT=3, NH=3, C=96, FF=384
// Round 15: R13 (best) with ff_fused reshaped to 64-row tiles ->
// 66.6 KB smem, (256,3) -> 24 warps/SM. Attention back to 384-thr R13.
// ---------------------------------------------------------------------------

#define T_TOK 401408

__device__ __nv_bfloat16 g_h  [(size_t)T_TOK * 128];  // attn output o
__device__ __nv_bfloat16 g_qkv[(size_t)T_TOK * 288];  // qkv; reused as h2 [T,96]
__device__ float         g_x1 [(size_t)T_TOK * 96];   // x + attn residual (fp32)

__device__ __nv_bfloat16 w_qkv[288 * 96];
__device__ __nv_bfloat16 w_out[96 * 96];
__device__ __nv_bfloat16 w_ff1[384 * 96];
__device__ __nv_bfloat16 w_ff2[96 * 384];

__device__ __forceinline__ uint32_t smem_u32(const void* p) {
    uint32_t a;
    asm("{ .reg .u64 t; cvta.to.shared.u64 t, %1; cvt.u32.u64 %0, t; }" : "=r"(a) : "l"(p));
    return a;
}
__device__ __forceinline__ uint32_t f2bf2(float lo, float hi) {
    __nv_bfloat162 h2 = __floats2bfloat162_rn(lo, hi);
    return *reinterpret_cast<uint32_t*>(&h2);
}
__device__ __forceinline__ void ldmx4(uint32_t* r, uint32_t addr) {
    asm volatile("ldmatrix.sync.aligned.m8n8.x4.shared.b16 {%0,%1,%2,%3}, [%4];"
                 : "=r"(r[0]), "=r"(r[1]), "=r"(r[2]), "=r"(r[3]) : "r"(addr));
}
__device__ __forceinline__ void ldmx4t(uint32_t* r, uint32_t addr) {
    asm volatile("ldmatrix.sync.aligned.m8n8.x4.trans.shared.b16 {%0,%1,%2,%3}, [%4];"
                 : "=r"(r[0]), "=r"(r[1]), "=r"(r[2]), "=r"(r[3]) : "r"(addr));
}
__device__ __forceinline__ void mma_bf16(float* c, const uint32_t* a, uint32_t b0, uint32_t b1) {
    asm volatile(
        "mma.sync.aligned.m16n8k16.row.col.f32.bf16.bf16.f32 "
        "{%0,%1,%2,%3}, {%4,%5,%6,%7}, {%8,%9}, {%0,%1,%2,%3};"
        : "+f"(c[0]), "+f"(c[1]), "+f"(c[2]), "+f"(c[3])
        : "r"(a[0]), "r"(a[1]), "r"(a[2]), "r"(a[3]), "r"(b0), "r"(b1));
}
__device__ __forceinline__ float tanh_ap(float x) {
    float y;
    asm("tanh.approx.f32 %0, %1;" : "=f"(y) : "f"(x));
    return y;
}
__device__ __forceinline__ float gelu_f(float v) {
    float u = 0.7978845608028654f * v * (1.0f + 0.044715f * v * v);
    return 0.5f * v * (1.0f + tanh_ap(u));
}

// ---------------------------------------------------------------------------
// Merged weight fp32 -> bf16 conversion (one launch, 216 blocks)
// ---------------------------------------------------------------------------
__global__ __launch_bounds__(256)
void cvt_all(const float* __restrict__ s0, __nv_bfloat16* __restrict__ d0,
             const float* __restrict__ s1, __nv_bfloat16* __restrict__ d1,
             const float* __restrict__ s2, __nv_bfloat16* __restrict__ d2,
             const float* __restrict__ s3, __nv_bfloat16* __restrict__ d3)
{
    int i = blockIdx.x * 256 + threadIdx.x;
    const float* s; __nv_bfloat16* d; int base;
    if (i < 13824)      { s = s0; d = d0; base = 0; }
    else if (i < 18432) { s = s1; d = d1; base = 13824; }
    else if (i < 36864) { s = s2; d = d2; base = 18432; }
    else                { s = s3; d = d3; base = 36864; }
    int j = (i - base) * 2;
    float2 f = *(const float2*)(s + j);
    *(uint32_t*)(d + j) = f2bf2(f.x, f.y);
}

// ---------------------------------------------------------------------------
// Fused LN1 + QKV GEMM (R8, unchanged).
// ---------------------------------------------------------------------------
__global__ __launch_bounds__(256, 2)
void qkv_fused(const float* __restrict__ x, const __nv_bfloat16* __restrict__ W,
               const float* __restrict__ bias,
               const float* __restrict__ lnw, const float* __restrict__ lnb,
               __nv_bfloat16* __restrict__ qkv)
{
    __shared__ __align__(16) __nv_bfloat16 As[128 * 104];
    __shared__ __align__(16) __nv_bfloat16 Bs[96 * 104];

    int tid = threadIdx.x, lane = tid & 31, wid = tid >> 5;
    int mw = wid >> 1, nw = wid & 1;
    int lrow = lane & 15, lk8 = (lane >> 4) << 3;
    size_t row0 = (size_t)blockIdx.x * 128;
    uint32_t sA = smem_u32(As), sB = smem_u32(Bs);

    {
        int r = tid >> 1, q = tid & 1;
        const float* xr = x + (row0 + r) * 96 + q * 48;
        float v[48];
        float s = 0.0f;
        #pragma unroll
        for (int i = 0; i < 12; ++i) {
            float4 f = ((const float4*)xr)[i];
            v[i*4] = f.x; v[i*4+1] = f.y; v[i*4+2] = f.z; v[i*4+3] = f.w;
            s += f.x + f.y + f.z + f.w;
        }
        s += __shfl_xor_sync(0xffffffffu, s, 1);
        float mu = s * (1.0f / 96.0f);
        float vv = 0.0f;
        #pragma unroll
        for (int i = 0; i < 48; ++i) { float d = v[i] - mu; vv += d * d; }
        vv += __shfl_xor_sync(0xffffffffu, vv, 1);
        float inv = rsqrtf(vv * (1.0f / 96.0f) + 1e-5f);
        #pragma unroll
        for (int i = 0; i < 24; ++i) {
            int col = q * 48 + i * 2;
            *(uint32_t*)(As + r * 104 + col) =
                f2bf2((v[i*2] - mu) * inv * lnw[col] + lnb[col],
                      (v[i*2+1] - mu) * inv * lnw[col+1] + lnb[col+1]);
        }
    }
    __syncthreads();

    uint32_t areg[6][2][4];
    #pragma unroll
    for (int ks = 0; ks < 6; ++ks)
        #pragma unroll
        for (int fm = 0; fm < 2; ++fm)
            ldmx4(areg[ks][fm],
                  sA + ((mw * 32 + fm * 16 + lrow) * 104 + ks * 16 + lk8) * 2);

    for (int c = 0; c < 3; ++c) {
        __syncthreads();
        for (int u = tid; u < 96 * 12; u += 256) {
            int n = u / 12, g = u % 12;
            *(uint4*)(Bs + n * 104 + g * 8) =
                *(const uint4*)(W + (size_t)(c * 96 + n) * 96 + g * 8);
        }
        __syncthreads();

        float acc[2][6][4];
        #pragma unroll
        for (int fm = 0; fm < 2; ++fm)
            #pragma unroll
            for (int fn = 0; fn < 6; ++fn)
                #pragma unroll
                for (int r = 0; r < 4; ++r) acc[fm][fn][r] = 0.0f;

        #pragma unroll
        for (int ks = 0; ks < 6; ++ks) {
            uint32_t bfr[3][4];
            #pragma unroll
            for (int f3 = 0; f3 < 3; ++f3)
                ldmx4(bfr[f3], sB + ((nw * 48 + f3 * 16 + lrow) * 104 + ks * 16 + lk8) * 2);
            #pragma unroll
            for (int fm = 0; fm < 2; ++fm)
                #pragma unroll
                for (int fn = 0; fn < 6; ++fn) {
                    int f3 = fn >> 1, od = fn & 1;
                    mma_bf16(acc[fm][fn], areg[ks][fm], bfr[f3][od], bfr[f3][od + 2]);
                }
        }

        #pragma unroll
        for (int fm = 0; fm < 2; ++fm)
            #pragma unroll
            for (int fn = 0; fn < 6; ++fn) {
                int col = c * 96 + nw * 48 + fn * 8 + (lane & 3) * 2;
                float b0 = bias[col], b1 = bias[col + 1];
                size_t r_lo = row0 + mw * 32 + fm * 16 + (lane >> 2);
                *(uint32_t*)(qkv + r_lo * 288 + col) =
                    f2bf2(acc[fm][fn][0] + b0, acc[fm][fn][1] + b1);
                *(uint32_t*)(qkv + (r_lo + 8) * 288 + col) =
                    f2bf2(acc[fm][fn][2] + b0, acc[fm][fn][3] + b1);
            }
    }
}

// ---------------------------------------------------------------------------
// Proj GEMM (128x96, K=96) + residual + fused LN2 (R13, confirmed win).
// ---------------------------------------------------------------------------
__global__ __launch_bounds__(256, 3)
void proj_ln(const __nv_bfloat16* __restrict__ A, const __nv_bfloat16* __restrict__ W,
             const float* __restrict__ bias, const float* __restrict__ res,
             float* __restrict__ out,
             const float* __restrict__ lnw, const float* __restrict__ lnb,
             __nv_bfloat16* __restrict__ h2)
{
    __shared__ __align__(16) __nv_bfloat16 sbuf[128 * 104 + 96 * 104];
    __nv_bfloat16* As = sbuf;
    __nv_bfloat16* Bs = sbuf + 128 * 104;

    int tid = threadIdx.x, wid = tid >> 5, lane = tid & 31;
    int mw = wid >> 1, nw = wid & 1;
    size_t row0 = (size_t)blockIdx.x * 128;

    for (int u = tid; u < 128 * 12; u += 256) {
        int r = u / 12, g = u % 12;
        *(uint4*)(As + r * 104 + g * 8) = *(const uint4*)(A + (row0 + r) * 128 + g * 8);
    }
    for (int u = tid; u < 96 * 12; u += 256) {
        int n = u / 12, g = u % 12;
        *(uint4*)(Bs + n * 104 + g * 8) = *(const uint4*)(W + (size_t)n * 96 + g * 8);
    }
    __syncthreads();

    uint32_t sAs = smem_u32(As), sBs = smem_u32(Bs);
    int lrow = lane & 15, lk8 = (lane >> 4) << 3;

    float c[2][6][4];
    #pragma unroll
    for (int fm = 0; fm < 2; ++fm)
        #pragma unroll
        for (int fn = 0; fn < 6; ++fn)
            #pragma unroll
            for (int r = 0; r < 4; ++r) c[fm][fn][r] = 0.0f;

    #pragma unroll
    for (int ks = 0; ks < 6; ++ks) {
        int k0 = ks * 16;
        uint32_t a[2][4];
        #pragma unroll
        for (int fm = 0; fm < 2; ++fm)
            ldmx4(a[fm], sAs + ((mw * 32 + fm * 16 + lrow) * 104 + k0 + lk8) * 2);
        uint32_t bfr[3][4];
        #pragma unroll
        for (int f3 = 0; f3 < 3; ++f3)
            ldmx4(bfr[f3], sBs + ((nw * 48 + f3 * 16 + lrow) * 104 + k0 + lk8) * 2);
        #pragma unroll
        for (int fm = 0; fm < 2; ++fm)
            #pragma unroll
            for (int fn = 0; fn < 6; ++fn) {
                int f3 = fn >> 1, od = fn & 1;
                mma_bf16(c[fm][fn], a[fm], bfr[f3][od], bfr[f3][od + 2]);
            }
    }
    __syncthreads();

    __nv_bfloat16* stg = sbuf;
    #pragma unroll
    for (int fm = 0; fm < 2; ++fm)
        #pragma unroll
        for (int fn = 0; fn < 6; ++fn) {
            int colg = nw * 48 + fn * 8 + (lane & 3) * 2;
            float b0 = bias[colg], b1 = bias[colg + 1];
            #pragma unroll
            for (int hh = 0; hh < 2; ++hh) {
                int rloc = mw * 32 + fm * 16 + (lane >> 2) + hh * 8;
                size_t rowg = row0 + rloc;
                float v0 = c[fm][fn][hh * 2]     + b0;
                float v1 = c[fm][fn][hh * 2 + 1] + b1;
                const float2 rr = *(const float2*)(res + rowg * 96 + colg);
                v0 += rr.x; v1 += rr.y;
                *(float2*)(out + rowg * 96 + colg) = make_float2(v0, v1);
                *(uint32_t*)(stg + rloc * 104 + colg) = f2bf2(v0, v1);
            }
        }
    __syncthreads();
    for (int r = wid; r < 128; r += 8) {
        float v0 = __bfloat162float(stg[r * 104 + lane]);
        float v1 = __bfloat162float(stg[r * 104 + lane + 32]);
        float v2 = __bfloat162float(stg[r * 104 + lane + 64]);
        float s = v0 + v1 + v2;
        #pragma unroll
        for (int o = 16; o; o >>= 1) s += __shfl_xor_sync(0xffffffffu, s, o);
        float mu = s * (1.0f / 96.0f);
        float d0 = v0 - mu, d1 = v1 - mu, d2 = v2 - mu;
        float vv = d0 * d0 + d1 * d1 + d2 * d2;
        #pragma unroll
        for (int o = 16; o; o >>= 1) vv += __shfl_xor_sync(0xffffffffu, vv, o);
        float inv = rsqrtf(vv * (1.0f / 96.0f) + 1e-5f);
        __nv_bfloat16* hr = h2 + (row0 + r) * 96;
        hr[lane]      = __float2bfloat16(d0 * inv * lnw[lane]      + lnb[lane]);
        hr[lane + 32] = __float2bfloat16(d1 * inv * lnw[lane + 32] + lnb[lane + 32]);
        hr[lane + 64] = __float2bfloat16(d2 * inv * lnw[lane + 64] + lnb[lane + 64]);
    }
}

// ---------------------------------------------------------------------------
// Fused FF (chunk-interleaved), 64-row tiles: smem 66.6 KB -> 3 CTA/SM.
// Warp tile 16x48; acc2 24 regs persistent. launch_bounds(256,3).
// ---------------------------------------------------------------------------
__global__ __launch_bounds__(256, 3)
void ff_fused(const __nv_bfloat16* __restrict__ h2, const __nv_bfloat16* __restrict__ W1,
              const float* __restrict__ b1v, const __nv_bfloat16* __restrict__ W2,
              const float* __restrict__ b2v, const float* __restrict__ res,
              float* __restrict__ out)
{
    extern __shared__ __align__(16) char dyn[];
    __nv_bfloat16* As  = (__nv_bfloat16*)dyn;    // 64*104
    __nv_bfloat16* FFs = As + 64 * 104;          // 64*104
    __nv_bfloat16* B1  = FFs + 64 * 104;         // 96*104
    __nv_bfloat16* B2  = B1 + 96 * 104;          // 96*104

    int tid = threadIdx.x, lane = tid & 31, wid = tid >> 5;
    int mw = wid >> 1, nw = wid & 1;               // mw 0..3 (16-row tile), nw 0..1
    int lrow = lane & 15, lk8 = (lane >> 4) << 3;
    size_t row0 = (size_t)blockIdx.x * 64;
    uint32_t sA = smem_u32(As), sF = smem_u32(FFs), sB1 = smem_u32(B1), sB2 = smem_u32(B2);

    for (int u = tid; u < 64 * 12; u += 256) {
        int r = u / 12, g = u % 12;
        *(uint4*)(As + r * 104 + g * 8) = *(const uint4*)(h2 + (row0 + r) * 96 + g * 8);
    }

    float acc2[6][4];
    #pragma unroll
    for (int fn = 0; fn < 6; ++fn)
        #pragma unroll
        for (int r = 0; r < 4; ++r) acc2[fn][r] = 0.0f;

    for (int c = 0; c < 4; ++c) {
        __syncthreads();   // prev stage2 reads of FFs/B2 done; As ready (c=0)
        for (int u = tid; u < 96 * 12; u += 256) {
            int n = u / 12, g = u % 12;
            *(uint4*)(B1 + n * 104 + g * 8) =
                *(const uint4*)(W1 + (size_t)(c * 96 + n) * 96 + g * 8);
            *(uint4*)(B2 + n * 104 + g * 8) =
                *(const uint4*)(W2 + (size_t)n * 384 + c * 96 + g * 8);
        }
        __syncthreads();

        // stage 1: acc1 = As(16 rows) @ B1_c^T
        float acc1[6][4];
        #pragma unroll
        for (int fn = 0; fn < 6; ++fn)
            #pragma unroll
            for (int r = 0; r < 4; ++r) acc1[fn][r] = 0.0f;

        #pragma unroll
        for (int ks = 0; ks < 6; ++ks) {
            uint32_t a[4];
            ldmx4(a, sA + ((mw * 16 + lrow) * 104 + ks * 16 + lk8) * 2);
            uint32_t bfr[3][4];
            #pragma unroll
            for (int f3 = 0; f3 < 3; ++f3)
                ldmx4(bfr[f3], sB1 + ((nw * 48 + f3 * 16 + lrow) * 104 + ks * 16 + lk8) * 2);
            #pragma unroll
            for (int fn = 0; fn < 6; ++fn) {
                int f3 = fn >> 1, od = fn & 1;
                mma_bf16(acc1[fn], a, bfr[f3][od], bfr[f3][od + 2]);
            }
        }

        // gelu + bias -> FFs
        #pragma unroll
        for (int fn = 0; fn < 6; ++fn) {
            int colc = nw * 48 + fn * 8 + (lane & 3) * 2;
            float b0 = b1v[c * 96 + colc], b1 = b1v[c * 96 + colc + 1];
            int rl = mw * 16 + (lane >> 2);
            *(uint32_t*)(FFs + rl * 104 + colc) =
                f2bf2(gelu_f(acc1[fn][0] + b0), gelu_f(acc1[fn][1] + b1));
            *(uint32_t*)(FFs + (rl + 8) * 104 + colc) =
                f2bf2(gelu_f(acc1[fn][2] + b0), gelu_f(acc1[fn][3] + b1));
        }
        __syncthreads();

        // stage 2: acc2 += FFs(16 rows) @ B2_c^T
        #pragma unroll
        for (int ks = 0; ks < 6; ++ks) {
            uint32_t a[4];
            ldmx4(a, sF + ((mw * 16 + lrow) * 104 + ks * 16 + lk8) * 2);
            uint32_t bfr[3][4];
            #pragma unroll
            for (int f3 = 0; f3 < 3; ++f3)
                ldmx4(bfr[f3], sB2 + ((nw * 48 + f3 * 16 + lrow) * 104 + ks * 16 + lk8) * 2);
            #pragma unroll
            for (int fn = 0; fn < 6; ++fn) {
                int f3 = fn >> 1, od = fn & 1;
                mma_bf16(acc2[fn], a, bfr[f3][od], bfr[f3][od + 2]);
            }
        }
    }

    // epilogue: + b2 + x1 residual -> out (fp32)
    #pragma unroll
    for (int fn = 0; fn < 6; ++fn) {
        int colg = nw * 48 + fn * 8 + (lane & 3) * 2;
        float b0 = b2v[colg], b1 = b2v[colg + 1];
        #pragma unroll
        for (int hh = 0; hh < 2; ++hh) {
            size_t rowg = row0 + mw * 16 + (lane >> 2) + hh * 8;
            float v0 = acc2[fn][hh * 2]     + b0;
            float v1 = acc2[fn][hh * 2 + 1] + b1;
            const float2 rr = *(const float2*)(res + rowg * 96 + colg);
            *(float2*)(out + rowg * 96 + colg) = make_float2(v0 + rr.x, v1 + rr.y);
        }
    }
}

// ---------------------------------------------------------------------------
// Tensor-core windowed attention (R13 384-thr, unconstrained regs).
// ---------------------------------------------------------------------------
__global__ __launch_bounds__(384)
void attn_mma(const __nv_bfloat16* __restrict__ qkv, __nv_bfloat16* __restrict__ o)
{
    __shared__ __nv_bfloat16 Qs[64][104];
    __shared__ __nv_bfloat16 Ks[64][104];
    __shared__ __nv_bfloat16 Vs[64][104];
    __shared__ int tokS[64];
    __shared__ int regS[64];

    int win = blockIdx.x;
    int b = win >> 6, w = win & 63;
    int wr = w >> 3, wc = w & 7;
    int tid = threadIdx.x, lane = tid & 31, wid = tid >> 5;

    if (tid < 64) {
        if (tid < 49) {
            int lr = tid / 7, lc = tid - lr * 7;
            int ri = wr * 7 + lr, rj = wc * 7 + lc;
            int oi = ri + 3; if (oi >= 56) oi -= 56;
            int oj = rj + 3; if (oj >= 56) oj -= 56;
            tokS[tid] = b * 3136 + oi * 56 + oj;
            regS[tid] = 3 * ((ri >= 49) + (ri >= 53)) + ((rj >= 49) + (rj >= 53));
        } else { tokS[tid] = 0; regS[tid] = -1; }
    }
    __syncthreads();

    for (int u = tid; u < 64 * 12 * 3; u += 384) {
        int tsel = u / 768;
        int rem = u - tsel * 768;
        int r = rem / 12, cg = rem % 12;
        uint4 v = make_uint4(0u, 0u, 0u, 0u);
        if (r < 49)
            v = *(const uint4*)(qkv + (size_t)tokS[r] * 288 + tsel * 96 + cg * 8);
        __nv_bfloat16* dst = (tsel == 0) ? &Qs[0][0] : (tsel == 1) ? &Ks[0][0] : &Vs[0][0];
        *(uint4*)(dst + r * 104 + cg * 8) = v;
    }
    __syncthreads();

    int head = wid >> 2;
    int mt   = wid & 3;
    int lrow = lane & 15;
    int lk8  = (lane >> 4) << 3;
    uint32_t sQ = smem_u32(&Qs[0][0]);
    uint32_t sK = smem_u32(&Ks[0][0]);
    uint32_t sV = smem_u32(&Vs[0][0]);

    float s[8][4];
    #pragma unroll
    for (int nt = 0; nt < 8; ++nt)
        #pragma unroll
        for (int r = 0; r < 4; ++r) s[nt][r] = 0.0f;

    #pragma unroll
    for (int kt = 0; kt < 2; ++kt) {
        uint32_t a[4];
        ldmx4(a, sQ + ((mt * 16 + lrow) * 104 + head * 32 + kt * 16 + lk8) * 2);
        #pragma unroll
        for (int nt16 = 0; nt16 < 4; ++nt16) {
            uint32_t bq[4];
            ldmx4(bq, sK + ((nt16 * 16 + lrow) * 104 + head * 32 + kt * 16 + lk8) * 2);
            mma_bf16(s[2 * nt16],     a, bq[0], bq[2]);
            mma_bf16(s[2 * nt16 + 1], a, bq[1], bq[3]);
        }
    }

    int r_lo = mt * 16 + (lane >> 2);
    int r_hi = r_lo + 8;
    int mreg_lo = regS[r_lo];
    int mreg_hi = regS[r_hi];
    int c0 = (lane & 3) * 2;
    const float scale = 0.17677669529663688f;

    float mx_lo = -1e30f, mx_hi = -1e30f;
    #pragma unroll
    for (int nt = 0; nt < 8; ++nt) {
        int j0 = nt * 8 + c0, j1 = j0 + 1;
        int rg0 = regS[j0], rg1 = regS[j1];
        float v0 = s[nt][0] * scale + ((rg0 != mreg_lo) ? -1e9f : 0.0f);
        float v1 = s[nt][1] * scale + ((rg1 != mreg_lo) ? -1e9f : 0.0f);
        float v2 = s[nt][2] * scale + ((rg0 != mreg_hi) ? -1e9f : 0.0f);
        float v3 = s[nt][3] * scale + ((rg1 != mreg_hi) ? -1e9f : 0.0f);
        s[nt][0] = v0; s[nt][1] = v1; s[nt][2] = v2; s[nt][3] = v3;
        mx_lo = fmaxf(mx_lo, fmaxf(v0, v1));
        mx_hi = fmaxf(mx_hi, fmaxf(v2, v3));
    }
    #pragma unroll
    for (int off = 1; off <= 2; off <<= 1) {
        mx_lo = fmaxf(mx_lo, __shfl_xor_sync(0xffffffffu, mx_lo, off));
        mx_hi = fmaxf(mx_hi, __shfl_xor_sync(0xffffffffu, mx_hi, off));
    }
    float sum_lo = 0.0f, sum_hi = 0.0f;
    #pragma unroll
    for (int nt = 0; nt < 8; ++nt) {
        float e0 = __expf(s[nt][0] - mx_lo);
        float e1 = __expf(s[nt][1] - mx_lo);
        float e2 = __expf(s[nt][2] - mx_hi);
        float e3 = __expf(s[nt][3] - mx_hi);
        s[nt][0] = e0; s[nt][1] = e1; s[nt][2] = e2; s[nt][3] = e3;
        sum_lo += e0 + e1; sum_hi += e2 + e3;
    }
    #pragma unroll
    for (int off = 1; off <= 2; off <<= 1) {
        sum_lo += __shfl_xor_sync(0xffffffffu, sum_lo, off);
        sum_hi += __shfl_xor_sync(0xffffffffu, sum_hi, off);
    }
    float inv_lo = 1.0f / sum_lo, inv_hi = 1.0f / sum_hi;
    #pragma unroll
    for (int nt = 0; nt < 8; ++nt) {
        s[nt][0] *= inv_lo; s[nt][1] *= inv_lo;
        s[nt][2] *= inv_hi; s[nt][3] *= inv_hi;
    }

    float ov[4][4];
    #pragma unroll
    for (int nt = 0; nt < 4; ++nt)
        #pragma unroll
        for (int r = 0; r < 4; ++r) ov[nt][r] = 0.0f;

    #pragma unroll
    for (int kt2 = 0; kt2 < 4; ++kt2) {
        uint32_t a[4];
        a[0] = f2bf2(s[2 * kt2][0],     s[2 * kt2][1]);
        a[1] = f2bf2(s[2 * kt2][2],     s[2 * kt2][3]);
        a[2] = f2bf2(s[2 * kt2 + 1][0], s[2 * kt2 + 1][1]);
        a[3] = f2bf2(s[2 * kt2 + 1][2], s[2 * kt2 + 1][3]);
        uint32_t bt0[4], bt1[4];
        ldmx4t(bt0, sV + ((kt2 * 16 + lrow) * 104 + head * 32 + lk8) * 2);
        ldmx4t(bt1, sV + ((kt2 * 16 + lrow) * 104 + head * 32 + 16 + lk8) * 2);
        mma_bf16(ov[0], a, bt0[0], bt0[1]);
        mma_bf16(ov[1], a, bt0[2], bt0[3]);
        mma_bf16(ov[2], a, bt1[0], bt1[1]);
        mma_bf16(ov[3], a, bt1[2], bt1[3]);
    }

    #pragma unroll
    for (int nt = 0; nt < 4; ++nt) {
        int col = head * 32 + nt * 8 + c0;
        if (r_lo < 49)
            *(uint32_t*)(o + (size_t)tokS[r_lo] * 128 + col) = f2bf2(ov[nt][0], ov[nt][1]);
        if (r_hi < 49)
            *(uint32_t*)(o + (size_t)tokS[r_hi] * 128 + col) = f2bf2(ov[nt][2], ov[nt][3]);
    }
}

// ---------------------------------------------------------------------------
// Launch
// ---------------------------------------------------------------------------
extern "C" void kernel_launch(void* const* d_in, const int* in_sizes, int n_in,
                              void* d_out, int out_size)
{
    const float* x     = (const float*)d_in[0];
    const float* qkv_w = (const float*)d_in[1];
    const float* qkv_b = (const float*)d_in[2];
    const float* out_w = (const float*)d_in[3];
    const float* out_b = (const float*)d_in[4];
    const float* ln1_w = (const float*)d_in[5];
    const float* ln1_b = (const float*)d_in[6];
    const float* ln2_w = (const float*)d_in[7];
    const float* ln2_b = (const float*)d_in[8];
    const float* ff1_w = (const float*)d_in[9];
    const float* ff1_b = (const float*)d_in[10];
    const float* ff2_w = (const float*)d_in[11];
    const float* ff2_b = (const float*)d_in[12];
    float* out = (float*)d_out;

    __nv_bfloat16 *p_h, *p_qkv;
    __nv_bfloat16 *pw_qkv, *pw_out, *pw_ff1, *pw_ff2;
    float *p_x1;
    cudaGetSymbolAddress((void**)&p_h,    g_h);
    cudaGetSymbolAddress((void**)&p_qkv,  g_qkv);
    cudaGetSymbolAddress((void**)&p_x1,   g_x1);
    cudaGetSymbolAddress((void**)&pw_qkv, w_qkv);
    cudaGetSymbolAddress((void**)&pw_out, w_out);
    cudaGetSymbolAddress((void**)&pw_ff1, w_ff1);
    cudaGetSymbolAddress((void**)&pw_ff2, w_ff2);

    const int s_ff = (64 * 104 * 2 + 96 * 104 * 2) * 2;   // 66,560 B
    cudaFuncSetAttribute(ff_fused, cudaFuncAttributeMaxDynamicSharedMemorySize, s_ff);

    // 0. weights fp32 -> bf16 (single launch)
    cvt_all<<<216, 256>>>(qkv_w, pw_qkv, out_w, pw_out, ff1_w, pw_ff1, ff2_w, pw_ff2);
    // 1. qkv = LN1(x) @ qkv_w^T + qkv_b        (bf16 [T,288])
    qkv_fused<<<T_TOK / 128, 256>>>(x, pw_qkv, qkv_b, ln1_w, ln1_b, p_qkv);
    // 2. o = windowed masked attention          (bf16 [T,128])
    attn_mma<<<8192, 384>>>(p_qkv, p_h);
    // 3. x1 = x + o @ out_w^T + out_b ; h2 = LN2(x1)  (h2 -> g_qkv, [T,96])
    proj_ln<<<T_TOK / 128, 256>>>(p_h, pw_out, out_b, x, p_x1, ln2_w, ln2_b, p_qkv);
    // 4. out = x1 + gelu(h2 @ ff1^T + b1) @ ff2^T + b2   (64-row tiles)
    ff_fused<<<T_TOK / 64, 256, s_ff>>>(p_qkv, pw_ff1, ff1_b, pw_ff2, ff2_b, p_x1, out);
}

// round 17
// speedup vs baseline: 1.0458x; 1.0458x over previous
#include <cuda_runtime.h>
#include <cuda_bf16.h>
#include <math.h>
#include <stdint.h>

// ---------------------------------------------------------------------------
// SwinTransformer block, B=128, FMAP=56, WS=7, SHIFT=3, NH=3, C=96, FF=384
// Round 17: R13 + attention output stored [T,96] (dense). The R16 __syncwarp
// in ff_fused was WRONG (cross-warp column halves) — block barrier restored.
// ---------------------------------------------------------------------------

#define T_TOK 401408

__device__ __nv_bfloat16 g_h  [(size_t)T_TOK * 96];   // attn output o [T,96]
__device__ __nv_bfloat16 g_qkv[(size_t)T_TOK * 288];  // qkv; reused as h2 [T,96]
__device__ float         g_x1 [(size_t)T_TOK * 96];   // x + attn residual (fp32)

__device__ __nv_bfloat16 w_qkv[288 * 96];
__device__ __nv_bfloat16 w_out[96 * 96];
__device__ __nv_bfloat16 w_ff1[384 * 96];
__device__ __nv_bfloat16 w_ff2[96 * 384];

__device__ __forceinline__ uint32_t smem_u32(const void* p) {
    uint32_t a;
    asm("{ .reg .u64 t; cvta.to.shared.u64 t, %1; cvt.u32.u64 %0, t; }" : "=r"(a) : "l"(p));
    return a;
}
__device__ __forceinline__ uint32_t f2bf2(float lo, float hi) {
    __nv_bfloat162 h2 = __floats2bfloat162_rn(lo, hi);
    return *reinterpret_cast<uint32_t*>(&h2);
}
__device__ __forceinline__ void ldmx4(uint32_t* r, uint32_t addr) {
    asm volatile("ldmatrix.sync.aligned.m8n8.x4.shared.b16 {%0,%1,%2,%3}, [%4];"
                 : "=r"(r[0]), "=r"(r[1]), "=r"(r[2]), "=r"(r[3]) : "r"(addr));
}
__device__ __forceinline__ void ldmx4t(uint32_t* r, uint32_t addr) {
    asm volatile("ldmatrix.sync.aligned.m8n8.x4.trans.shared.b16 {%0,%1,%2,%3}, [%4];"
                 : "=r"(r[0]), "=r"(r[1]), "=r"(r[2]), "=r"(r[3]) : "r"(addr));
}
__device__ __forceinline__ void mma_bf16(float* c, const uint32_t* a, uint32_t b0, uint32_t b1) {
    asm volatile(
        "mma.sync.aligned.m16n8k16.row.col.f32.bf16.bf16.f32 "
        "{%0,%1,%2,%3}, {%4,%5,%6,%7}, {%8,%9}, {%0,%1,%2,%3};"
        : "+f"(c[0]), "+f"(c[1]), "+f"(c[2]), "+f"(c[3])
        : "r"(a[0]), "r"(a[1]), "r"(a[2]), "r"(a[3]), "r"(b0), "r"(b1));
}
__device__ __forceinline__ float tanh_ap(float x) {
    float y;
    asm("tanh.approx.f32 %0, %1;" : "=f"(y) : "f"(x));
    return y;
}
__device__ __forceinline__ float gelu_f(float v) {
    float u = 0.7978845608028654f * v * (1.0f + 0.044715f * v * v);
    return 0.5f * v * (1.0f + tanh_ap(u));
}

// ---------------------------------------------------------------------------
// Merged weight fp32 -> bf16 conversion (one launch, 216 blocks)
// ---------------------------------------------------------------------------
__global__ __launch_bounds__(256)
void cvt_all(const float* __restrict__ s0, __nv_bfloat16* __restrict__ d0,
             const float* __restrict__ s1, __nv_bfloat16* __restrict__ d1,
             const float* __restrict__ s2, __nv_bfloat16* __restrict__ d2,
             const float* __restrict__ s3, __nv_bfloat16* __restrict__ d3)
{
    int i = blockIdx.x * 256 + threadIdx.x;
    const float* s; __nv_bfloat16* d; int base;
    if (i < 13824)      { s = s0; d = d0; base = 0; }
    else if (i < 18432) { s = s1; d = d1; base = 13824; }
    else if (i < 36864) { s = s2; d = d2; base = 18432; }
    else                { s = s3; d = d3; base = 36864; }
    int j = (i - base) * 2;
    float2 f = *(const float2*)(s + j);
    *(uint32_t*)(d + j) = f2bf2(f.x, f.y);
}

// ---------------------------------------------------------------------------
// Fused LN1 + QKV GEMM (R8, unchanged).
// ---------------------------------------------------------------------------
__global__ __launch_bounds__(256, 2)
void qkv_fused(const float* __restrict__ x, const __nv_bfloat16* __restrict__ W,
               const float* __restrict__ bias,
               const float* __restrict__ lnw, const float* __restrict__ lnb,
               __nv_bfloat16* __restrict__ qkv)
{
    __shared__ __align__(16) __nv_bfloat16 As[128 * 104];
    __shared__ __align__(16) __nv_bfloat16 Bs[96 * 104];

    int tid = threadIdx.x, lane = tid & 31, wid = tid >> 5;
    int mw = wid >> 1, nw = wid & 1;
    int lrow = lane & 15, lk8 = (lane >> 4) << 3;
    size_t row0 = (size_t)blockIdx.x * 128;
    uint32_t sA = smem_u32(As), sB = smem_u32(Bs);

    {
        int r = tid >> 1, q = tid & 1;
        const float* xr = x + (row0 + r) * 96 + q * 48;
        float v[48];
        float s = 0.0f;
        #pragma unroll
        for (int i = 0; i < 12; ++i) {
            float4 f = ((const float4*)xr)[i];
            v[i*4] = f.x; v[i*4+1] = f.y; v[i*4+2] = f.z; v[i*4+3] = f.w;
            s += f.x + f.y + f.z + f.w;
        }
        s += __shfl_xor_sync(0xffffffffu, s, 1);
        float mu = s * (1.0f / 96.0f);
        float vv = 0.0f;
        #pragma unroll
        for (int i = 0; i < 48; ++i) { float d = v[i] - mu; vv += d * d; }
        vv += __shfl_xor_sync(0xffffffffu, vv, 1);
        float inv = rsqrtf(vv * (1.0f / 96.0f) + 1e-5f);
        #pragma unroll
        for (int i = 0; i < 24; ++i) {
            int col = q * 48 + i * 2;
            *(uint32_t*)(As + r * 104 + col) =
                f2bf2((v[i*2] - mu) * inv * lnw[col] + lnb[col],
                      (v[i*2+1] - mu) * inv * lnw[col+1] + lnb[col+1]);
        }
    }
    __syncthreads();

    uint32_t areg[6][2][4];
    #pragma unroll
    for (int ks = 0; ks < 6; ++ks)
        #pragma unroll
        for (int fm = 0; fm < 2; ++fm)
            ldmx4(areg[ks][fm],
                  sA + ((mw * 32 + fm * 16 + lrow) * 104 + ks * 16 + lk8) * 2);

    for (int c = 0; c < 3; ++c) {
        __syncthreads();
        for (int u = tid; u < 96 * 12; u += 256) {
            int n = u / 12, g = u % 12;
            *(uint4*)(Bs + n * 104 + g * 8) =
                *(const uint4*)(W + (size_t)(c * 96 + n) * 96 + g * 8);
        }
        __syncthreads();

        float acc[2][6][4];
        #pragma unroll
        for (int fm = 0; fm < 2; ++fm)
            #pragma unroll
            for (int fn = 0; fn < 6; ++fn)
                #pragma unroll
                for (int r = 0; r < 4; ++r) acc[fm][fn][r] = 0.0f;

        #pragma unroll
        for (int ks = 0; ks < 6; ++ks) {
            uint32_t bfr[3][4];
            #pragma unroll
            for (int f3 = 0; f3 < 3; ++f3)
                ldmx4(bfr[f3], sB + ((nw * 48 + f3 * 16 + lrow) * 104 + ks * 16 + lk8) * 2);
            #pragma unroll
            for (int fm = 0; fm < 2; ++fm)
                #pragma unroll
                for (int fn = 0; fn < 6; ++fn) {
                    int f3 = fn >> 1, od = fn & 1;
                    mma_bf16(acc[fm][fn], areg[ks][fm], bfr[f3][od], bfr[f3][od + 2]);
                }
        }

        #pragma unroll
        for (int fm = 0; fm < 2; ++fm)
            #pragma unroll
            for (int fn = 0; fn < 6; ++fn) {
                int col = c * 96 + nw * 48 + fn * 8 + (lane & 3) * 2;
                float b0 = bias[col], b1 = bias[col + 1];
                size_t r_lo = row0 + mw * 32 + fm * 16 + (lane >> 2);
                *(uint32_t*)(qkv + r_lo * 288 + col) =
                    f2bf2(acc[fm][fn][0] + b0, acc[fm][fn][1] + b1);
                *(uint32_t*)(qkv + (r_lo + 8) * 288 + col) =
                    f2bf2(acc[fm][fn][2] + b0, acc[fm][fn][3] + b1);
            }
    }
}

// ---------------------------------------------------------------------------
// Proj GEMM (128x96, K=96) + residual + fused LN2. o input stride 96.
// ---------------------------------------------------------------------------
__global__ __launch_bounds__(256, 3)
void proj_ln(const __nv_bfloat16* __restrict__ A, const __nv_bfloat16* __restrict__ W,
             const float* __restrict__ bias, const float* __restrict__ res,
             float* __restrict__ out,
             const float* __restrict__ lnw, const float* __restrict__ lnb,
             __nv_bfloat16* __restrict__ h2)
{
    __shared__ __align__(16) __nv_bfloat16 sbuf[128 * 104 + 96 * 104];
    __nv_bfloat16* As = sbuf;
    __nv_bfloat16* Bs = sbuf + 128 * 104;

    int tid = threadIdx.x, wid = tid >> 5, lane = tid & 31;
    int mw = wid >> 1, nw = wid & 1;
    size_t row0 = (size_t)blockIdx.x * 128;

    for (int u = tid; u < 128 * 12; u += 256) {
        int r = u / 12, g = u % 12;
        *(uint4*)(As + r * 104 + g * 8) = *(const uint4*)(A + (row0 + r) * 96 + g * 8);
    }
    for (int u = tid; u < 96 * 12; u += 256) {
        int n = u / 12, g = u % 12;
        *(uint4*)(Bs + n * 104 + g * 8) = *(const uint4*)(W + (size_t)n * 96 + g * 8);
    }
    __syncthreads();

    uint32_t sAs = smem_u32(As), sBs = smem_u32(Bs);
    int lrow = lane & 15, lk8 = (lane >> 4) << 3;

    float c[2][6][4];
    #pragma unroll
    for (int fm = 0; fm < 2; ++fm)
        #pragma unroll
        for (int fn = 0; fn < 6; ++fn)
            #pragma unroll
            for (int r = 0; r < 4; ++r) c[fm][fn][r] = 0.0f;

    #pragma unroll
    for (int ks = 0; ks < 6; ++ks) {
        int k0 = ks * 16;
        uint32_t a[2][4];
        #pragma unroll
        for (int fm = 0; fm < 2; ++fm)
            ldmx4(a[fm], sAs + ((mw * 32 + fm * 16 + lrow) * 104 + k0 + lk8) * 2);
        uint32_t bfr[3][4];
        #pragma unroll
        for (int f3 = 0; f3 < 3; ++f3)
            ldmx4(bfr[f3], sBs + ((nw * 48 + f3 * 16 + lrow) * 104 + k0 + lk8) * 2);
        #pragma unroll
        for (int fm = 0; fm < 2; ++fm)
            #pragma unroll
            for (int fn = 0; fn < 6; ++fn) {
                int f3 = fn >> 1, od = fn & 1;
                mma_bf16(c[fm][fn], a[fm], bfr[f3][od], bfr[f3][od + 2]);
            }
    }
    __syncthreads();

    __nv_bfloat16* stg = sbuf;
    #pragma unroll
    for (int fm = 0; fm < 2; ++fm)
        #pragma unroll
        for (int fn = 0; fn < 6; ++fn) {
            int colg = nw * 48 + fn * 8 + (lane & 3) * 2;
            float b0 = bias[colg], b1 = bias[colg + 1];
            #pragma unroll
            for (int hh = 0; hh < 2; ++hh) {
                int rloc = mw * 32 + fm * 16 + (lane >> 2) + hh * 8;
                size_t rowg = row0 + rloc;
                float v0 = c[fm][fn][hh * 2]     + b0;
                float v1 = c[fm][fn][hh * 2 + 1] + b1;
                const float2 rr = *(const float2*)(res + rowg * 96 + colg);
                v0 += rr.x; v1 += rr.y;
                *(float2*)(out + rowg * 96 + colg) = make_float2(v0, v1);
                *(uint32_t*)(stg + rloc * 104 + colg) = f2bf2(v0, v1);
            }
        }
    __syncthreads();
    for (int r = wid; r < 128; r += 8) {
        float v0 = __bfloat162float(stg[r * 104 + lane]);
        float v1 = __bfloat162float(stg[r * 104 + lane + 32]);
        float v2 = __bfloat162float(stg[r * 104 + lane + 64]);
        float s = v0 + v1 + v2;
        #pragma unroll
        for (int o = 16; o; o >>= 1) s += __shfl_xor_sync(0xffffffffu, s, o);
        float mu = s * (1.0f / 96.0f);
        float d0 = v0 - mu, d1 = v1 - mu, d2 = v2 - mu;
        float vv = d0 * d0 + d1 * d1 + d2 * d2;
        #pragma unroll
        for (int o = 16; o; o >>= 1) vv += __shfl_xor_sync(0xffffffffu, vv, o);
        float inv = rsqrtf(vv * (1.0f / 96.0f) + 1e-5f);
        __nv_bfloat16* hr = h2 + (row0 + r) * 96;
        hr[lane]      = __float2bfloat16(d0 * inv * lnw[lane]      + lnb[lane]);
        hr[lane + 32] = __float2bfloat16(d1 * inv * lnw[lane + 32] + lnb[lane + 32]);
        hr[lane + 64] = __float2bfloat16(d2 * inv * lnw[lane + 64] + lnb[lane + 64]);
    }
}

// ---------------------------------------------------------------------------
// Fused FF (chunk-interleaved, R13: full block barriers). h2 in stride 96.
// ---------------------------------------------------------------------------
__global__ __launch_bounds__(256, 2)
void ff_fused(const __nv_bfloat16* __restrict__ h2, const __nv_bfloat16* __restrict__ W1,
              const float* __restrict__ b1v, const __nv_bfloat16* __restrict__ W2,
              const float* __restrict__ b2v, const float* __restrict__ res,
              float* __restrict__ out)
{
    extern __shared__ __align__(16) char dyn[];
    __nv_bfloat16* As  = (__nv_bfloat16*)dyn;    // 128*104
    __nv_bfloat16* FFs = As + 128 * 104;         // 128*104
    __nv_bfloat16* B1  = FFs + 128 * 104;        // 96*104
    __nv_bfloat16* B2  = B1 + 96 * 104;          // 96*104

    int tid = threadIdx.x, lane = tid & 31, wid = tid >> 5;
    int mw = wid >> 1, nw = wid & 1;
    int lrow = lane & 15, lk8 = (lane >> 4) << 3;
    size_t row0 = (size_t)blockIdx.x * 128;
    uint32_t sA = smem_u32(As), sF = smem_u32(FFs), sB1 = smem_u32(B1), sB2 = smem_u32(B2);

    for (int u = tid; u < 128 * 12; u += 256) {
        int r = u / 12, g = u % 12;
        *(uint4*)(As + r * 104 + g * 8) = *(const uint4*)(h2 + (row0 + r) * 96 + g * 8);
    }

    float acc2[2][6][4];
    #pragma unroll
    for (int fm = 0; fm < 2; ++fm)
        #pragma unroll
        for (int fn = 0; fn < 6; ++fn)
            #pragma unroll
            for (int r = 0; r < 4; ++r) acc2[fm][fn][r] = 0.0f;

    for (int c = 0; c < 4; ++c) {
        __syncthreads();
        for (int u = tid; u < 96 * 12; u += 256) {
            int n = u / 12, g = u % 12;
            *(uint4*)(B1 + n * 104 + g * 8) =
                *(const uint4*)(W1 + (size_t)(c * 96 + n) * 96 + g * 8);
            *(uint4*)(B2 + n * 104 + g * 8) =
                *(const uint4*)(W2 + (size_t)n * 384 + c * 96 + g * 8);
        }
        __syncthreads();

        float acc1[2][6][4];
        #pragma unroll
        for (int fm = 0; fm < 2; ++fm)
            #pragma unroll
            for (int fn = 0; fn < 6; ++fn)
                #pragma unroll
                for (int r = 0; r < 4; ++r) acc1[fm][fn][r] = 0.0f;

        #pragma unroll
        for (int ks = 0; ks < 6; ++ks) {
            uint32_t a[2][4];
            #pragma unroll
            for (int fm = 0; fm < 2; ++fm)
                ldmx4(a[fm], sA + ((mw * 32 + fm * 16 + lrow) * 104 + ks * 16 + lk8) * 2);
            uint32_t bfr[3][4];
            #pragma unroll
            for (int f3 = 0; f3 < 3; ++f3)
                ldmx4(bfr[f3], sB1 + ((nw * 48 + f3 * 16 + lrow) * 104 + ks * 16 + lk8) * 2);
            #pragma unroll
            for (int fm = 0; fm < 2; ++fm)
                #pragma unroll
                for (int fn = 0; fn < 6; ++fn) {
                    int f3 = fn >> 1, od = fn & 1;
                    mma_bf16(acc1[fm][fn], a[fm], bfr[f3][od], bfr[f3][od + 2]);
                }
        }

        #pragma unroll
        for (int fm = 0; fm < 2; ++fm)
            #pragma unroll
            for (int fn = 0; fn < 6; ++fn) {
                int colc = nw * 48 + fn * 8 + (lane & 3) * 2;
                float b0 = b1v[c * 96 + colc], b1 = b1v[c * 96 + colc + 1];
                int rl = mw * 32 + fm * 16 + (lane >> 2);
                *(uint32_t*)(FFs + rl * 104 + colc) =
                    f2bf2(gelu_f(acc1[fm][fn][0] + b0), gelu_f(acc1[fm][fn][1] + b1));
                *(uint32_t*)(FFs + (rl + 8) * 104 + colc) =
                    f2bf2(gelu_f(acc1[fm][fn][2] + b0), gelu_f(acc1[fm][fn][3] + b1));
            }
        __syncthreads();   // cross-warp: nw halves of each row written by different warps

        #pragma unroll
        for (int ks = 0; ks < 6; ++ks) {
            uint32_t a[2][4];
            #pragma unroll
            for (int fm = 0; fm < 2; ++fm)
                ldmx4(a[fm], sF + ((mw * 32 + fm * 16 + lrow) * 104 + ks * 16 + lk8) * 2);
            uint32_t bfr[3][4];
            #pragma unroll
            for (int f3 = 0; f3 < 3; ++f3)
                ldmx4(bfr[f3], sB2 + ((nw * 48 + f3 * 16 + lrow) * 104 + ks * 16 + lk8) * 2);
            #pragma unroll
            for (int fm = 0; fm < 2; ++fm)
                #pragma unroll
                for (int fn = 0; fn < 6; ++fn) {
                    int f3 = fn >> 1, od = fn & 1;
                    mma_bf16(acc2[fm][fn], a[fm], bfr[f3][od], bfr[f3][od + 2]);
                }
        }
    }

    #pragma unroll
    for (int fm = 0; fm < 2; ++fm)
        #pragma unroll
        for (int fn = 0; fn < 6; ++fn) {
            int colg = nw * 48 + fn * 8 + (lane & 3) * 2;
            float b0 = b2v[colg], b1 = b2v[colg + 1];
            #pragma unroll
            for (int hh = 0; hh < 2; ++hh) {
                size_t rowg = row0 + mw * 32 + fm * 16 + (lane >> 2) + hh * 8;
                float v0 = acc2[fm][fn][hh * 2]     + b0;
                float v1 = acc2[fm][fn][hh * 2 + 1] + b1;
                const float2 rr = *(const float2*)(res + rowg * 96 + colg);
                *(float2*)(out + rowg * 96 + colg) = make_float2(v0 + rr.x, v1 + rr.y);
            }
        }
}

// ---------------------------------------------------------------------------
// Tensor-core windowed attention (R13, 384 thr). o out stride 96.
// ---------------------------------------------------------------------------
__global__ __launch_bounds__(384)
void attn_mma(const __nv_bfloat16* __restrict__ qkv, __nv_bfloat16* __restrict__ o)
{
    __shared__ __nv_bfloat16 Qs[64][104];
    __shared__ __nv_bfloat16 Ks[64][104];
    __shared__ __nv_bfloat16 Vs[64][104];
    __shared__ int tokS[64];
    __shared__ int regS[64];

    int win = blockIdx.x;
    int b = win >> 6, w = win & 63;
    int wr = w >> 3, wc = w & 7;
    int tid = threadIdx.x, lane = tid & 31, wid = tid >> 5;

    if (tid < 64) {
        if (tid < 49) {
            int lr = tid / 7, lc = tid - lr * 7;
            int ri = wr * 7 + lr, rj = wc * 7 + lc;
            int oi = ri + 3; if (oi >= 56) oi -= 56;
            int oj = rj + 3; if (oj >= 56) oj -= 56;
            tokS[tid] = b * 3136 + oi * 56 + oj;
            regS[tid] = 3 * ((ri >= 49) + (ri >= 53)) + ((rj >= 49) + (rj >= 53));
        } else { tokS[tid] = 0; regS[tid] = -1; }
    }
    __syncthreads();

    for (int u = tid; u < 64 * 12 * 3; u += 384) {
        int tsel = u / 768;
        int rem = u - tsel * 768;
        int r = rem / 12, cg = rem % 12;
        uint4 v = make_uint4(0u, 0u, 0u, 0u);
        if (r < 49)
            v = *(const uint4*)(qkv + (size_t)tokS[r] * 288 + tsel * 96 + cg * 8);
        __nv_bfloat16* dst = (tsel == 0) ? &Qs[0][0] : (tsel == 1) ? &Ks[0][0] : &Vs[0][0];
        *(uint4*)(dst + r * 104 + cg * 8) = v;
    }
    __syncthreads();

    int head = wid >> 2;
    int mt   = wid & 3;
    int lrow = lane & 15;
    int lk8  = (lane >> 4) << 3;
    uint32_t sQ = smem_u32(&Qs[0][0]);
    uint32_t sK = smem_u32(&Ks[0][0]);
    uint32_t sV = smem_u32(&Vs[0][0]);

    float s[8][4];
    #pragma unroll
    for (int nt = 0; nt < 8; ++nt)
        #pragma unroll
        for (int r = 0; r < 4; ++r) s[nt][r] = 0.0f;

    #pragma unroll
    for (int kt = 0; kt < 2; ++kt) {
        uint32_t a[4];
        ldmx4(a, sQ + ((mt * 16 + lrow) * 104 + head * 32 + kt * 16 + lk8) * 2);
        #pragma unroll
        for (int nt16 = 0; nt16 < 4; ++nt16) {
            uint32_t bq[4];
            ldmx4(bq, sK + ((nt16 * 16 + lrow) * 104 + head * 32 + kt * 16 + lk8) * 2);
            mma_bf16(s[2 * nt16],     a, bq[0], bq[2]);
            mma_bf16(s[2 * nt16 + 1], a, bq[1], bq[3]);
        }
    }

    int r_lo = mt * 16 + (lane >> 2);
    int r_hi = r_lo + 8;
    int mreg_lo = regS[r_lo];
    int mreg_hi = regS[r_hi];
    int c0 = (lane & 3) * 2;
    const float scale = 0.17677669529663688f;

    float mx_lo = -1e30f, mx_hi = -1e30f;
    #pragma unroll
    for (int nt = 0; nt < 8; ++nt) {
        int j0 = nt * 8 + c0, j1 = j0 + 1;
        int rg0 = regS[j0], rg1 = regS[j1];
        float v0 = s[nt][0] * scale + ((rg0 != mreg_lo) ? -1e9f : 0.0f);
        float v1 = s[nt][1] * scale + ((rg1 != mreg_lo) ? -1e9f : 0.0f);
        float v2 = s[nt][2] * scale + ((rg0 != mreg_hi) ? -1e9f : 0.0f);
        float v3 = s[nt][3] * scale + ((rg1 != mreg_hi) ? -1e9f : 0.0f);
        s[nt][0] = v0; s[nt][1] = v1; s[nt][2] = v2; s[nt][3] = v3;
        mx_lo = fmaxf(mx_lo, fmaxf(v0, v1));
        mx_hi = fmaxf(mx_hi, fmaxf(v2, v3));
    }
    #pragma unroll
    for (int off = 1; off <= 2; off <<= 1) {
        mx_lo = fmaxf(mx_lo, __shfl_xor_sync(0xffffffffu, mx_lo, off));
        mx_hi = fmaxf(mx_hi, __shfl_xor_sync(0xffffffffu, mx_hi, off));
    }
    float sum_lo = 0.0f, sum_hi = 0.0f;
    #pragma unroll
    for (int nt = 0; nt < 8; ++nt) {
        float e0 = __expf(s[nt][0] - mx_lo);
        float e1 = __expf(s[nt][1] - mx_lo);
        float e2 = __expf(s[nt][2] - mx_hi);
        float e3 = __expf(s[nt][3] - mx_hi);
        s[nt][0] = e0; s[nt][1] = e1; s[nt][2] = e2; s[nt][3] = e3;
        sum_lo += e0 + e1; sum_hi += e2 + e3;
    }
    #pragma unroll
    for (int off = 1; off <= 2; off <<= 1) {
        sum_lo += __shfl_xor_sync(0xffffffffu, sum_lo, off);
        sum_hi += __shfl_xor_sync(0xffffffffu, sum_hi, off);
    }
    float inv_lo = 1.0f / sum_lo, inv_hi = 1.0f / sum_hi;
    #pragma unroll
    for (int nt = 0; nt < 8; ++nt) {
        s[nt][0] *= inv_lo; s[nt][1] *= inv_lo;
        s[nt][2] *= inv_hi; s[nt][3] *= inv_hi;
    }

    float ov[4][4];
    #pragma unroll
    for (int nt = 0; nt < 4; ++nt)
        #pragma unroll
        for (int r = 0; r < 4; ++r) ov[nt][r] = 0.0f;

    #pragma unroll
    for (int kt2 = 0; kt2 < 4; ++kt2) {
        uint32_t a[4];
        a[0] = f2bf2(s[2 * kt2][0],     s[2 * kt2][1]);
        a[1] = f2bf2(s[2 * kt2][2],     s[2 * kt2][3]);
        a[2] = f2bf2(s[2 * kt2 + 1][0], s[2 * kt2 + 1][1]);
        a[3] = f2bf2(s[2 * kt2 + 1][2], s[2 * kt2 + 1][3]);
        uint32_t bt0[4], bt1[4];
        ldmx4t(bt0, sV + ((kt2 * 16 + lrow) * 104 + head * 32 + lk8) * 2);
        ldmx4t(bt1, sV + ((kt2 * 16 + lrow) * 104 + head * 32 + 16 + lk8) * 2);
        mma_bf16(ov[0], a, bt0[0], bt0[1]);
        mma_bf16(ov[1], a, bt0[2], bt0[3]);
        mma_bf16(ov[2], a, bt1[0], bt1[1]);
        mma_bf16(ov[3], a, bt1[2], bt1[3]);
    }

    #pragma unroll
    for (int nt = 0; nt < 4; ++nt) {
        int col = head * 32 + nt * 8 + c0;
        if (r_lo < 49)
            *(uint32_t*)(o + (size_t)tokS[r_lo] * 96 + col) = f2bf2(ov[nt][0], ov[nt][1]);
        if (r_hi < 49)
            *(uint32_t*)(o + (size_t)tokS[r_hi] * 96 + col) = f2bf2(ov[nt][2], ov[nt][3]);
    }
}

// ---------------------------------------------------------------------------
// Launch
// ---------------------------------------------------------------------------
extern "C" void kernel_launch(void* const* d_in, const int* in_sizes, int n_in,
                              void* d_out, int out_size)
{
    const float* x     = (const float*)d_in[0];
    const float* qkv_w = (const float*)d_in[1];
    const float* qkv_b = (const float*)d_in[2];
    const float* out_w = (const float*)d_in[3];
    const float* out_b = (const float*)d_in[4];
    const float* ln1_w = (const float*)d_in[5];
    const float* ln1_b = (const float*)d_in[6];
    const float* ln2_w = (const float*)d_in[7];
    const float* ln2_b = (const float*)d_in[8];
    const float* ff1_w = (const float*)d_in[9];
    const float* ff1_b = (const float*)d_in[10];
    const float* ff2_w = (const float*)d_in[11];
    const float* ff2_b = (const float*)d_in[12];
    float* out = (float*)d_out;

    __nv_bfloat16 *p_h, *p_qkv;
    __nv_bfloat16 *pw_qkv, *pw_out, *pw_ff1, *pw_ff2;
    float *p_x1;
    cudaGetSymbolAddress((void**)&p_h,    g_h);
    cudaGetSymbolAddress((void**)&p_qkv,  g_qkv);
    cudaGetSymbolAddress((void**)&p_x1,   g_x1);
    cudaGetSymbolAddress((void**)&pw_qkv, w_qkv);
    cudaGetSymbolAddress((void**)&pw_out, w_out);
    cudaGetSymbolAddress((void**)&pw_ff1, w_ff1);
    cudaGetSymbolAddress((void**)&pw_ff2, w_ff2);

    const int s_ff = (128 * 104 * 2 + 96 * 104 * 2) * 2;   // 93,184 B
    cudaFuncSetAttribute(ff_fused, cudaFuncAttributeMaxDynamicSharedMemorySize, s_ff);

    // 0. weights fp32 -> bf16 (single launch)
    cvt_all<<<216, 256>>>(qkv_w, pw_qkv, out_w, pw_out, ff1_w, pw_ff1, ff2_w, pw_ff2);
    // 1. qkv = LN1(x) @ qkv_w^T + qkv_b        (bf16 [T,288])
    qkv_fused<<<T_TOK / 128, 256>>>(x, pw_qkv, qkv_b, ln1_w, ln1_b, p_qkv);
    // 2. o = windowed masked attention          (bf16 [T,96])
    attn_mma<<<8192, 384>>>(p_qkv, p_h);
    // 3. x1 = x + o @ out_w^T + out_b ; h2 = LN2(x1)  (h2 -> g_qkv, [T,96])
    proj_ln<<<T_TOK / 128, 256>>>(p_h, pw_out, out_b, x, p_x1, ln2_w, ln2_b, p_qkv);
    // 4. out = x1 + gelu(h2 @ ff1^T + b1) @ ff2^T + b2   (fused, no ff buffer)
    ff_fused<<<T_TOK / 128, 256, s_ff>>>(p_qkv, pw_ff1, ff1_b, pw_ff2, ff2_b, p_x1, out);
}